// round 12
// baseline (speedup 1.0000x reference)
#include <cuda_runtime.h>
#include <cuda_bf16.h>
#include <cstdint>

#define NN 50000
#define EE 500000
#define HH 128
#define GG 256

// ---------------- scratch (device globals; no allocs allowed) ----------------
static __device__ __align__(16) __nv_bfloat16 g_hb0[(size_t)NN * HH];  // gemm1 out / agg2 out
static __device__ __align__(16) __nv_bfloat16 g_hb1[(size_t)NN * HH];  // gemm2(fused agg1) out
static __device__ float g_deg[NN];
static __device__ float g_dinv[NN];
static __device__ float g_sn[NN];      // self-loop coeff = 1/deg
static __device__ int   g_cnt[NN];
static __device__ int   g_off[NN];
static __device__ int   g_part[256];   // scan partials
static __device__ int   g_pos[EE];
static __device__ __align__(8) int2 g_edge[EE];   // CSR: {src, normalized w as bits}
static __device__ __align__(16) float g_pooled[GG * HH];
static __device__ float g_gcnt[GG];

// ---------------- helpers ----------------
__device__ __forceinline__ float4 bf4(uint2 u) {
    __nv_bfloat162 a = *reinterpret_cast<__nv_bfloat162*>(&u.x);
    __nv_bfloat162 b = *reinterpret_cast<__nv_bfloat162*>(&u.y);
    float2 fa = __bfloat1622float2(a), fb = __bfloat1622float2(b);
    return make_float4(fa.x, fa.y, fb.x, fb.y);
}
__device__ __forceinline__ uint2 pk4(float4 v) {
    __nv_bfloat162 a = __float22bfloat162_rn(make_float2(v.x, v.y));
    __nv_bfloat162 b = __float22bfloat162_rn(make_float2(v.z, v.w));
    uint2 u;
    u.x = *reinterpret_cast<uint32_t*>(&a);
    u.y = *reinterpret_cast<uint32_t*>(&b);
    return u;
}
// fp32 quad -> (hi, lo) bf16x2 pairs
__device__ __forceinline__ void split4(float4 v, uint2& ph, uint2& pl) {
    __nv_bfloat16 h0 = __float2bfloat16(v.x), h1 = __float2bfloat16(v.y);
    __nv_bfloat16 h2 = __float2bfloat16(v.z), h3 = __float2bfloat16(v.w);
    __nv_bfloat16 l0 = __float2bfloat16(v.x - __bfloat162float(h0));
    __nv_bfloat16 l1 = __float2bfloat16(v.y - __bfloat162float(h1));
    __nv_bfloat16 l2 = __float2bfloat16(v.z - __bfloat162float(h2));
    __nv_bfloat16 l3 = __float2bfloat16(v.w - __bfloat162float(h3));
    ph.x = ((uint32_t)__bfloat16_as_ushort(h1) << 16) | __bfloat16_as_ushort(h0);
    ph.y = ((uint32_t)__bfloat16_as_ushort(h3) << 16) | __bfloat16_as_ushort(h2);
    pl.x = ((uint32_t)__bfloat16_as_ushort(l1) << 16) | __bfloat16_as_ushort(l0);
    pl.y = ((uint32_t)__bfloat16_as_ushort(l3) << 16) | __bfloat16_as_ushort(l2);
}

// ---------------- init ----------------
__global__ void setup_kernel() {
    int i = blockIdx.x * blockDim.x + threadIdx.x;
    if (i < NN) { g_deg[i] = 1.0f; g_cnt[i] = 0; }
    if (i < GG * HH) g_pooled[i] = 0.0f;
    if (i < GG) g_gcnt[i] = 0.0f;
}

// 2 edges per thread
__global__ void count_kernel(const int2* __restrict__ dst2, const float2* __restrict__ ew2) {
    int e = blockIdx.x * blockDim.x + threadIdx.x;
    if (e >= EE / 2) return;
    int2 d = dst2[e];
    float2 w = ew2[e];
    atomicAdd(&g_deg[d.x], w.x);
    g_pos[2 * e]     = atomicAdd(&g_cnt[d.x], 1);
    atomicAdd(&g_deg[d.y], w.y);
    g_pos[2 * e + 1] = atomicAdd(&g_cnt[d.y], 1);
}

// scanA: per-block local exclusive scan into g_off, block totals into g_part.
// (Two kernels, NOT a single-kernel spin scan: a spin on cross-block publication
//  deadlocks when the concurrent GEMM holds the SMs — the kernel boundary is the
//  forward-progress guarantee.)
__global__ void scanA_kernel() {        // 196 blocks x 256
    __shared__ int sh[256];
    int t = threadIdx.x;
    int i = blockIdx.x * 256 + t;
    int v = (i < NN) ? g_cnt[i] : 0;
    sh[t] = v;
    __syncthreads();
    #pragma unroll
    for (int s = 1; s < 256; s <<= 1) {
        int u = (t >= s) ? sh[t - s] : 0;
        __syncthreads();
        sh[t] += u;
        __syncthreads();
    }
    if (i < NN) g_off[i] = sh[t] - v;
    if (t == 255) g_part[blockIdx.x] = sh[255];
}
// scanB: every block re-scans the 196 partials locally, adds base, fuses dinv
__global__ void scanB_kernel() {        // 196 blocks x 256
    __shared__ int sp[256];
    int t = threadIdx.x;
    const int nb = (NN + 255) / 256;    // 196
    sp[t] = (t < nb) ? g_part[t] : 0;
    __syncthreads();
    #pragma unroll
    for (int s = 1; s < 256; s <<= 1) {
        int u = (t >= s) ? sp[t - s] : 0;
        __syncthreads();
        sp[t] += u;
        __syncthreads();
    }
    int base = blockIdx.x ? sp[blockIdx.x - 1] : 0;
    int i = blockIdx.x * 256 + t;
    if (i < NN) {
        g_off[i] += base;
        float d = rsqrtf(g_deg[i]);   // deg >= 1 always
        g_dinv[i] = d;
        g_sn[i] = d * d;
    }
}

// 2 edges per thread
__global__ void scatter_kernel(const int2* __restrict__ src2, const int2* __restrict__ dst2,
                               const float2* __restrict__ ew2) {
    int e = blockIdx.x * blockDim.x + threadIdx.x;
    if (e >= EE / 2) return;
    int2 s = src2[e];
    int2 d = dst2[e];
    float2 w = ew2[e];
    int i0 = g_off[d.x] + g_pos[2 * e];
    g_edge[i0] = make_int2(s.x, __float_as_int(g_dinv[s.x] * w.x * g_dinv[d.x]));
    int i1 = g_off[d.y] + g_pos[2 * e + 1];
    g_edge[i1] = make_int2(s.y, __float_as_int(g_dinv[s.y] * w.y * g_dinv[d.y]));
}

// ---------------- HMMA GEMM: C[NN x 128] = A[NN x 128] @ W^T, bf16 out --------
// MODE 0: A fp32 (x), hi/lo split, 3 MMA passes.  MODE 1: fused agg1 prologue
// from bf16 hb0 via CSR (A exactly bf16), 2 MMA passes. W converted in-kernel.
#define SROW 136
#define OA_H 0
#define OA_L (1 * 34816)
#define OW_H (2 * 34816)
#define OW_L (3 * 34816)
#define GSMEM_BYTES (4 * 34816)

__device__ __forceinline__ void mma_bf16(float* c, const uint32_t* a, const uint32_t* b) {
    asm volatile(
        "mma.sync.aligned.m16n8k16.row.col.f32.bf16.bf16.f32 "
        "{%0,%1,%2,%3}, {%4,%5,%6,%7}, {%8,%9}, {%0,%1,%2,%3};"
        : "+f"(c[0]), "+f"(c[1]), "+f"(c[2]), "+f"(c[3])
        : "r"(a[0]), "r"(a[1]), "r"(a[2]), "r"(a[3]), "r"(b[0]), "r"(b[1]));
}

template<int MODE>
__global__ void __launch_bounds__(256) gemm_mma_kernel(
    const void* __restrict__ Ain,
    const float* __restrict__ W,       // fp32 weights, converted in-kernel
    const float* __restrict__ bias,    // MODE 1: agg bias
    uint32_t* __restrict__ C           // bf16x2-packed output
) {
    extern __shared__ __align__(16) unsigned char smem[];
    int t = threadIdx.x;
    int rowBase = blockIdx.x * 128;
    int warp = t >> 5, lane = t & 31;

    if (MODE == 0) {
        const float* A = (const float*)Ain;
        #pragma unroll
        for (int i = 0; i < 16; i++) {
            int idx = t + i * 256;
            int row = idx >> 5;
            int col = (idx & 31) << 2;
            float4 v = make_float4(0.f, 0.f, 0.f, 0.f);
            int gr = rowBase + row;
            if (gr < NN) v = *(const float4*)(A + (size_t)gr * HH + col);
            uint2 ph, pl;
            split4(v, ph, pl);
            uint32_t off = (uint32_t)(row * SROW + col) * 2;
            *(uint2*)(smem + OA_H + off) = ph;
            *(uint2*)(smem + OA_L + off) = pl;
        }
    } else {
        // fused agg1: aggregate bf16 hb0 rows via CSR, +bias, relu -> A tile
        const uint2* hb = (const uint2*)Ain;
        float4 b = *(const float4*)(bias + (lane << 2));
        #pragma unroll 1
        for (int rr = 0; rr < 16; rr++) {
            int row = warp * 16 + rr;
            int n = rowBase + row;
            float4 acc = make_float4(0.f, 0.f, 0.f, 0.f);
            if (n < NN) {
                float sn = g_sn[n];
                float4 hv = bf4(hb[(size_t)n * 32 + lane]);
                acc = make_float4(hv.x * sn, hv.y * sn, hv.z * sn, hv.w * sn);
                float4 acc2 = make_float4(0.f, 0.f, 0.f, 0.f);
                int o = g_off[n], c = g_cnt[n];
                const int2* ep = g_edge + o;
                int j = 0;
                for (; j + 1 < c; j += 2) {
                    int2 e0 = ep[j], e1 = ep[j + 1];
                    float w0 = __int_as_float(e0.y), w1 = __int_as_float(e1.y);
                    float4 v0 = bf4(hb[(size_t)e0.x * 32 + lane]);
                    float4 v1 = bf4(hb[(size_t)e1.x * 32 + lane]);
                    acc.x += v0.x * w0; acc.y += v0.y * w0; acc.z += v0.z * w0; acc.w += v0.w * w0;
                    acc2.x += v1.x * w1; acc2.y += v1.y * w1; acc2.z += v1.z * w1; acc2.w += v1.w * w1;
                }
                if (j < c) {
                    int2 e0 = ep[j];
                    float w0 = __int_as_float(e0.y);
                    float4 v0 = bf4(hb[(size_t)e0.x * 32 + lane]);
                    acc.x += v0.x * w0; acc.y += v0.y * w0; acc.z += v0.z * w0; acc.w += v0.w * w0;
                }
                acc.x = fmaxf(acc.x + acc2.x + b.x, 0.f);
                acc.y = fmaxf(acc.y + acc2.y + b.y, 0.f);
                acc.z = fmaxf(acc.z + acc2.z + b.z, 0.f);
                acc.w = fmaxf(acc.w + acc2.w + b.w, 0.f);
            }
            *(uint2*)(smem + OA_H + (uint32_t)(row * SROW + (lane << 2)) * 2) = pk4(acc);
        }
    }
    // W fp32 -> bf16 hi/lo into smem
    #pragma unroll
    for (int i = 0; i < 16; i++) {
        int idx = t + i * 256;
        int row = idx >> 5;
        int col = (idx & 31) << 2;
        float4 v = *(const float4*)(W + (size_t)row * HH + col);
        uint2 ph, pl;
        split4(v, ph, pl);
        uint32_t off = (uint32_t)(row * SROW + col) * 2;
        *(uint2*)(smem + OW_H + off) = ph;
        *(uint2*)(smem + OW_L + off) = pl;
    }
    __syncthreads();

    int mrow = (warp >> 1) * 32;
    int ncol = (warp & 1) * 64;
    int qrow = lane >> 2, qp = lane & 3;

    float acc[2][8][4];
    #pragma unroll
    for (int mt = 0; mt < 2; mt++)
        #pragma unroll
        for (int nt = 0; nt < 8; nt++)
            #pragma unroll
            for (int q = 0; q < 4; q++) acc[mt][nt][q] = 0.f;

    #pragma unroll
    for (int k0 = 0; k0 < HH; k0 += 16) {
        int cb = k0 + qp * 2;
        uint32_t ah[2][4], al[2][4], wh[8][2], wl[8][2];
        #pragma unroll
        for (int mt = 0; mt < 2; mt++) {
            int r = mrow + mt * 16 + qrow;
            uint32_t o00 = (uint32_t)(r * SROW + cb) * 2;
            uint32_t o10 = o00 + 8u * SROW * 2;
            ah[mt][0] = *(const uint32_t*)(smem + OA_H + o00);
            ah[mt][1] = *(const uint32_t*)(smem + OA_H + o10);
            ah[mt][2] = *(const uint32_t*)(smem + OA_H + o00 + 16);
            ah[mt][3] = *(const uint32_t*)(smem + OA_H + o10 + 16);
            if (MODE == 0) {
                al[mt][0] = *(const uint32_t*)(smem + OA_L + o00);
                al[mt][1] = *(const uint32_t*)(smem + OA_L + o10);
                al[mt][2] = *(const uint32_t*)(smem + OA_L + o00 + 16);
                al[mt][3] = *(const uint32_t*)(smem + OA_L + o10 + 16);
            }
        }
        #pragma unroll
        for (int nt = 0; nt < 8; nt++) {
            int n = ncol + nt * 8 + qrow;
            uint32_t o = (uint32_t)(n * SROW + cb) * 2;
            wh[nt][0] = *(const uint32_t*)(smem + OW_H + o);
            wh[nt][1] = *(const uint32_t*)(smem + OW_H + o + 16);
            wl[nt][0] = *(const uint32_t*)(smem + OW_L + o);
            wl[nt][1] = *(const uint32_t*)(smem + OW_L + o + 16);
        }
        #pragma unroll
        for (int mt = 0; mt < 2; mt++)
            #pragma unroll
            for (int nt = 0; nt < 8; nt++) {
                mma_bf16(acc[mt][nt], ah[mt], wh[nt]);
                mma_bf16(acc[mt][nt], ah[mt], wl[nt]);
                if (MODE == 0) mma_bf16(acc[mt][nt], al[mt], wh[nt]);
            }
    }

    #pragma unroll
    for (int mt = 0; mt < 2; mt++) {
        int r0 = rowBase + mrow + mt * 16 + qrow;
        #pragma unroll
        for (int nt = 0; nt < 8; nt++) {
            int cc = ncol + nt * 8 + qp * 2;
            if (r0 < NN) {
                __nv_bfloat162 p = __float22bfloat162_rn(make_float2(acc[mt][nt][0], acc[mt][nt][1]));
                C[(size_t)r0 * 64 + (cc >> 1)] = *reinterpret_cast<uint32_t*>(&p);
            }
            if (r0 + 8 < NN) {
                __nv_bfloat162 p = __float22bfloat162_rn(make_float2(acc[mt][nt][2], acc[mt][nt][3]));
                C[(size_t)(r0 + 8) * 64 + (cc >> 1)] = *reinterpret_cast<uint32_t*>(&p);
            }
        }
    }
}

// ---------------- agg2: out[n] = relu(h[n]/deg + sum h[s]*norm + b), bf16 out ---
__global__ void agg_kernel(const __nv_bfloat16* __restrict__ h,
                           const float* __restrict__ bias, uint2* __restrict__ outp) {
    int w = (blockIdx.x * blockDim.x + threadIdx.x) >> 5;
    int lane = threadIdx.x & 31;
    if (w >= NN) return;
    int n = w;
    float sn = g_sn[n];
    const uint2* hb = (const uint2*)h;
    float4 hv = bf4(hb[(size_t)n * 32 + lane]);
    float4 acc = make_float4(hv.x * sn, hv.y * sn, hv.z * sn, hv.w * sn);
    float4 acc2 = make_float4(0.f, 0.f, 0.f, 0.f);
    int o = g_off[n], c = g_cnt[n];
    const int2* ep = g_edge + o;
    int j = 0;
    for (; j + 1 < c; j += 2) {
        int2 e0 = ep[j], e1 = ep[j + 1];
        float w0 = __int_as_float(e0.y), w1 = __int_as_float(e1.y);
        float4 v0 = bf4(hb[(size_t)e0.x * 32 + lane]);
        float4 v1 = bf4(hb[(size_t)e1.x * 32 + lane]);
        acc.x += v0.x * w0; acc.y += v0.y * w0; acc.z += v0.z * w0; acc.w += v0.w * w0;
        acc2.x += v1.x * w1; acc2.y += v1.y * w1; acc2.z += v1.z * w1; acc2.w += v1.w * w1;
    }
    if (j < c) {
        int2 e0 = ep[j];
        float w0 = __int_as_float(e0.y);
        float4 v0 = bf4(hb[(size_t)e0.x * 32 + lane]);
        acc.x += v0.x * w0; acc.y += v0.y * w0; acc.z += v0.z * w0; acc.w += v0.w * w0;
    }
    float4 b = *reinterpret_cast<const float4*>(bias + (lane << 2));
    float4 r = make_float4(fmaxf(acc.x + acc2.x + b.x, 0.f), fmaxf(acc.y + acc2.y + b.y, 0.f),
                           fmaxf(acc.z + acc2.z + b.z, 0.f), fmaxf(acc.w + acc2.w + b.w, 0.f));
    outp[(size_t)n * 32 + lane] = pk4(r);
}

// ---------------- pooling (bf16 in, batch sorted; run-accumulate + atomics) -----
#define CHUNK 32
__global__ void pool_kernel(const __nv_bfloat16* __restrict__ h, const int* __restrict__ batch) {
    int w = (blockIdx.x * blockDim.x + threadIdx.x) >> 5;
    int lane = threadIdx.x & 31;
    int start = w * CHUNK;
    if (start >= NN) return;
    int end = min(NN, start + CHUNK);
    const uint2* hb = (const uint2*)h;
    int cur = batch[start];
    float4 acc = make_float4(0.f, 0.f, 0.f, 0.f);
    float cnt = 0.f;
    for (int i = start; i < end; i++) {
        int g = batch[i];
        if (g != cur) {
            float* p = &g_pooled[(size_t)cur * HH + (lane << 2)];
            atomicAdd(p + 0, acc.x); atomicAdd(p + 1, acc.y);
            atomicAdd(p + 2, acc.z); atomicAdd(p + 3, acc.w);
            if (lane == 0) atomicAdd(&g_gcnt[cur], cnt);
            acc = make_float4(0.f, 0.f, 0.f, 0.f); cnt = 0.f; cur = g;
        }
        float4 v = bf4(hb[(size_t)i * 32 + lane]);
        acc.x += v.x; acc.y += v.y; acc.z += v.z; acc.w += v.w;
        cnt += 1.f;
    }
    float* p = &g_pooled[(size_t)cur * HH + (lane << 2)];
    atomicAdd(p + 0, acc.x); atomicAdd(p + 1, acc.y);
    atomicAdd(p + 2, acc.z); atomicAdd(p + 3, acc.w);
    if (lane == 0) atomicAdd(&g_gcnt[cur], cnt);
}

// ---------------- head MLP ----------------
__global__ void mlp_kernel(const float* __restrict__ fW1, const float* __restrict__ fb1,
                           const float* __restrict__ fW2, const float* __restrict__ fb2,
                           float* __restrict__ out) {
    __shared__ float p[HH];
    __shared__ float red[4];
    int g = blockIdx.x, j = threadIdx.x;
    float c = fmaxf(g_gcnt[g], 1.0f);
    p[j] = g_pooled[(size_t)g * HH + j] / c;
    __syncthreads();
    float acc = fb1[j];
    #pragma unroll 8
    for (int k = 0; k < HH; k++) acc += p[k] * fW1[(size_t)j * HH + k];
    float o = fmaxf(acc, 0.f) * fW2[j];
    #pragma unroll
    for (int s = 16; s > 0; s >>= 1) o += __shfl_down_sync(0xffffffffu, o, s);
    if ((j & 31) == 0) red[j >> 5] = o;
    __syncthreads();
    if (j == 0) out[g] = red[0] + red[1] + red[2] + red[3] + fb2[0];
}

// ---------------- launch ----------------
extern "C" void kernel_launch(void* const* d_in, const int* in_sizes, int n_in,
                              void* d_out, int out_size) {
    const float* x     = (const float*)d_in[0];
    const int*   ei    = (const int*)d_in[1];
    const float* ea    = (const float*)d_in[2];
    const int*   batch = (const int*)d_in[3];
    const float* W1    = (const float*)d_in[4];
    const float* b1    = (const float*)d_in[5];
    const float* W2    = (const float*)d_in[6];
    const float* b2    = (const float*)d_in[7];
    const float* fW1   = (const float*)d_in[8];
    const float* fb1   = (const float*)d_in[9];
    const float* fW2   = (const float*)d_in[10];
    const float* fb2   = (const float*)d_in[11];
    float* out = (float*)d_out;

    const int* src = ei;
    const int* dst = ei + EE;

    void *ph0, *ph1;
    cudaGetSymbolAddress(&ph0, g_hb0);
    cudaGetSymbolAddress(&ph1, g_hb1);
    __nv_bfloat16* hb0 = (__nv_bfloat16*)ph0;
    __nv_bfloat16* hb1 = (__nv_bfloat16*)ph1;

    cudaFuncSetAttribute(gemm_mma_kernel<0>, cudaFuncAttributeMaxDynamicSharedMemorySize, GSMEM_BYTES);
    cudaFuncSetAttribute(gemm_mma_kernel<1>, cudaFuncAttributeMaxDynamicSharedMemorySize, GSMEM_BYTES);

    const int tb = 256;
    const int nblk = (NN + tb - 1) / tb;        // 196
    const int e2blk = (EE / 2 + tb - 1) / tb;   // 977
    const int ggrid = (NN + 127) / 128;         // 391

    cudaStream_t s2 = 0;
    cudaEvent_t evA = 0, evB = 0;
    bool par = (cudaStreamCreateWithFlags(&s2, cudaStreamNonBlocking) == cudaSuccess);
    if (par) par = (cudaEventCreateWithFlags(&evA, cudaEventDisableTiming) == cudaSuccess);
    if (par) par = (cudaEventCreateWithFlags(&evB, cudaEventDisableTiming) == cudaSuccess);
    cudaStream_t sc = par ? s2 : (cudaStream_t)0;

    if (par) {
        cudaEventRecord(evA, 0);
        cudaStreamWaitEvent(s2, evA, 0);
    }
    // CSR branch (side stream): init -> count -> scanA -> scanB -> scatter
    setup_kernel<<<nblk, tb, 0, sc>>>();
    count_kernel<<<e2blk, tb, 0, sc>>>((const int2*)dst, (const float2*)ea);
    scanA_kernel<<<nblk, tb, 0, sc>>>();
    scanB_kernel<<<nblk, tb, 0, sc>>>();
    scatter_kernel<<<e2blk, tb, 0, sc>>>((const int2*)src, (const int2*)dst, (const float2*)ea);
    // GEMM1 (main stream, starts immediately — converts W1 in-kernel)
    gemm_mma_kernel<0><<<ggrid, 256, GSMEM_BYTES>>>(x, W1, (const float*)0, (uint32_t*)hb0);
    if (par) {
        cudaEventRecord(evB, s2);
        cudaStreamWaitEvent(0, evB, 0);
    }

    // GEMM2 with fused agg1 prologue, then agg2 (bf16 out), pool, MLP head
    gemm_mma_kernel<1><<<ggrid, 256, GSMEM_BYTES>>>(hb0, W2, b1, (uint32_t*)hb1);
    agg_kernel<<<((NN * 32) + tb - 1) / tb, tb>>>(hb1, b2, (uint2*)hb0);

    int pwarps = (NN + CHUNK - 1) / CHUNK;
    pool_kernel<<<((pwarps * 32) + tb - 1) / tb, tb>>>(hb0, batch);
    mlp_kernel<<<GG, HH>>>(fW1, fb1, fW2, fb2, out);
}

// round 13
// speedup vs baseline: 1.4004x; 1.4004x over previous
#include <cuda_runtime.h>
#include <cuda_bf16.h>
#include <cstdint>

#define NN 50000
#define EE 500000
#define HH 128
#define GG 256

// ---------------- scratch (device globals; no allocs allowed) ----------------
static __device__ __align__(16) __nv_bfloat16 g_hb0[(size_t)NN * HH];  // gemm1 out / gemm2 out
static __device__ __align__(16) __nv_bfloat16 g_hb1[(size_t)NN * HH];  // agg1 out / agg2 out
static __device__ float g_deg[NN];
static __device__ float g_dinv[NN];
static __device__ float g_sn[NN];      // self-loop coeff = 1/deg
static __device__ int   g_cnt[NN];
static __device__ int   g_off[NN];
static __device__ int   g_part[256];   // scan partials
static __device__ int   g_pos[EE];
static __device__ __align__(8) int2 g_edge[EE];   // CSR: {src, normalized w as bits}
static __device__ __align__(16) float g_pooled[GG * HH];
static __device__ float g_gcnt[GG];

// ---------------- helpers ----------------
__device__ __forceinline__ float4 bf4(uint2 u) {
    __nv_bfloat162 a = *reinterpret_cast<__nv_bfloat162*>(&u.x);
    __nv_bfloat162 b = *reinterpret_cast<__nv_bfloat162*>(&u.y);
    float2 fa = __bfloat1622float2(a), fb = __bfloat1622float2(b);
    return make_float4(fa.x, fa.y, fb.x, fb.y);
}
__device__ __forceinline__ uint2 pk4(float4 v) {
    __nv_bfloat162 a = __float22bfloat162_rn(make_float2(v.x, v.y));
    __nv_bfloat162 b = __float22bfloat162_rn(make_float2(v.z, v.w));
    uint2 u;
    u.x = *reinterpret_cast<uint32_t*>(&a);
    u.y = *reinterpret_cast<uint32_t*>(&b);
    return u;
}
// fp32 quad -> (hi, lo) bf16x2 pairs
__device__ __forceinline__ void split4(float4 v, uint2& ph, uint2& pl) {
    __nv_bfloat16 h0 = __float2bfloat16(v.x), h1 = __float2bfloat16(v.y);
    __nv_bfloat16 h2 = __float2bfloat16(v.z), h3 = __float2bfloat16(v.w);
    __nv_bfloat16 l0 = __float2bfloat16(v.x - __bfloat162float(h0));
    __nv_bfloat16 l1 = __float2bfloat16(v.y - __bfloat162float(h1));
    __nv_bfloat16 l2 = __float2bfloat16(v.z - __bfloat162float(h2));
    __nv_bfloat16 l3 = __float2bfloat16(v.w - __bfloat162float(h3));
    ph.x = ((uint32_t)__bfloat16_as_ushort(h1) << 16) | __bfloat16_as_ushort(h0);
    ph.y = ((uint32_t)__bfloat16_as_ushort(h3) << 16) | __bfloat16_as_ushort(h2);
    pl.x = ((uint32_t)__bfloat16_as_ushort(l1) << 16) | __bfloat16_as_ushort(l0);
    pl.y = ((uint32_t)__bfloat16_as_ushort(l3) << 16) | __bfloat16_as_ushort(l2);
}

// ---------------- init ----------------
__global__ void setup_kernel() {
    int i = blockIdx.x * blockDim.x + threadIdx.x;
    if (i < NN) { g_deg[i] = 1.0f; g_cnt[i] = 0; }
    if (i < GG * HH) g_pooled[i] = 0.0f;
    if (i < GG) g_gcnt[i] = 0.0f;
}

// 2 edges per thread
__global__ void count_kernel(const int2* __restrict__ dst2, const float2* __restrict__ ew2) {
    int e = blockIdx.x * blockDim.x + threadIdx.x;
    if (e >= EE / 2) return;
    int2 d = dst2[e];
    float2 w = ew2[e];
    atomicAdd(&g_deg[d.x], w.x);
    g_pos[2 * e]     = atomicAdd(&g_cnt[d.x], 1);
    atomicAdd(&g_deg[d.y], w.y);
    g_pos[2 * e + 1] = atomicAdd(&g_cnt[d.y], 1);
}

// scanA: per-block local exclusive scan into g_off, block totals into g_part.
// (Two kernels — a cross-block spin scan deadlocks under concurrent GEMM.)
__global__ void scanA_kernel() {        // 196 blocks x 256
    __shared__ int sh[256];
    int t = threadIdx.x;
    int i = blockIdx.x * 256 + t;
    int v = (i < NN) ? g_cnt[i] : 0;
    sh[t] = v;
    __syncthreads();
    #pragma unroll
    for (int s = 1; s < 256; s <<= 1) {
        int u = (t >= s) ? sh[t - s] : 0;
        __syncthreads();
        sh[t] += u;
        __syncthreads();
    }
    if (i < NN) g_off[i] = sh[t] - v;
    if (t == 255) g_part[blockIdx.x] = sh[255];
}
// scanB: every block re-scans the 196 partials locally, adds base, fuses dinv
__global__ void scanB_kernel() {        // 196 blocks x 256
    __shared__ int sp[256];
    int t = threadIdx.x;
    const int nb = (NN + 255) / 256;    // 196
    sp[t] = (t < nb) ? g_part[t] : 0;
    __syncthreads();
    #pragma unroll
    for (int s = 1; s < 256; s <<= 1) {
        int u = (t >= s) ? sp[t - s] : 0;
        __syncthreads();
        sp[t] += u;
        __syncthreads();
    }
    int base = blockIdx.x ? sp[blockIdx.x - 1] : 0;
    int i = blockIdx.x * 256 + t;
    if (i < NN) {
        g_off[i] += base;
        float d = rsqrtf(g_deg[i]);   // deg >= 1 always
        g_dinv[i] = d;
        g_sn[i] = d * d;
    }
}

// 2 edges per thread
__global__ void scatter_kernel(const int2* __restrict__ src2, const int2* __restrict__ dst2,
                               const float2* __restrict__ ew2) {
    int e = blockIdx.x * blockDim.x + threadIdx.x;
    if (e >= EE / 2) return;
    int2 s = src2[e];
    int2 d = dst2[e];
    float2 w = ew2[e];
    int i0 = g_off[d.x] + g_pos[2 * e];
    g_edge[i0] = make_int2(s.x, __float_as_int(g_dinv[s.x] * w.x * g_dinv[d.x]));
    int i1 = g_off[d.y] + g_pos[2 * e + 1];
    g_edge[i1] = make_int2(s.y, __float_as_int(g_dinv[s.y] * w.y * g_dinv[d.y]));
}

// ---------------- HMMA GEMM: C[NN x 128] = A[NN x 128] @ W^T, bf16 out --------
// MODE 0: A fp32, hi/lo split, 3 MMA passes.  MODE 1: A bf16 (plain copy), 2
// passes.  W fp32 -> bf16 hi/lo converted in the prologue (same bytes read).
#define SROW 136
#define OA_H 0
#define OA_L (1 * 34816)
#define OW_H (2 * 34816)
#define OW_L (3 * 34816)
#define GSMEM_BYTES (4 * 34816)

__device__ __forceinline__ void mma_bf16(float* c, const uint32_t* a, const uint32_t* b) {
    asm volatile(
        "mma.sync.aligned.m16n8k16.row.col.f32.bf16.bf16.f32 "
        "{%0,%1,%2,%3}, {%4,%5,%6,%7}, {%8,%9}, {%0,%1,%2,%3};"
        : "+f"(c[0]), "+f"(c[1]), "+f"(c[2]), "+f"(c[3])
        : "r"(a[0]), "r"(a[1]), "r"(a[2]), "r"(a[3]), "r"(b[0]), "r"(b[1]));
}

template<int MODE>
__global__ void __launch_bounds__(256) gemm_mma_kernel(
    const void* __restrict__ Ain,
    const float* __restrict__ W,       // fp32 weights, converted in-kernel
    uint32_t* __restrict__ C           // bf16x2-packed output
) {
    extern __shared__ __align__(16) unsigned char smem[];
    int t = threadIdx.x;
    int rowBase = blockIdx.x * 128;

    if (MODE == 0) {
        const float* A = (const float*)Ain;
        #pragma unroll
        for (int i = 0; i < 16; i++) {
            int idx = t + i * 256;
            int row = idx >> 5;
            int col = (idx & 31) << 2;
            float4 v = make_float4(0.f, 0.f, 0.f, 0.f);
            int gr = rowBase + row;
            if (gr < NN) v = *(const float4*)(A + (size_t)gr * HH + col);
            uint2 ph, pl;
            split4(v, ph, pl);
            uint32_t off = (uint32_t)(row * SROW + col) * 2;
            *(uint2*)(smem + OA_H + off) = ph;
            *(uint2*)(smem + OA_L + off) = pl;
        }
    } else {
        const uint2* A = (const uint2*)Ain;   // bf16 rows: 32 uint2 per row
        #pragma unroll
        for (int i = 0; i < 16; i++) {
            int idx = t + i * 256;
            int row = idx >> 5;
            int col = (idx & 31) << 2;
            uint2 v = make_uint2(0u, 0u);
            int gr = rowBase + row;
            if (gr < NN) v = A[(size_t)gr * 32 + (idx & 31)];
            *(uint2*)(smem + OA_H + (uint32_t)(row * SROW + col) * 2) = v;
        }
    }
    // W fp32 -> bf16 hi/lo into smem
    #pragma unroll
    for (int i = 0; i < 16; i++) {
        int idx = t + i * 256;
        int row = idx >> 5;
        int col = (idx & 31) << 2;
        float4 v = *(const float4*)(W + (size_t)row * HH + col);
        uint2 ph, pl;
        split4(v, ph, pl);
        uint32_t off = (uint32_t)(row * SROW + col) * 2;
        *(uint2*)(smem + OW_H + off) = ph;
        *(uint2*)(smem + OW_L + off) = pl;
    }
    __syncthreads();

    int warp = t >> 5, lane = t & 31;
    int mrow = (warp >> 1) * 32;
    int ncol = (warp & 1) * 64;
    int qrow = lane >> 2, qp = lane & 3;

    float acc[2][8][4];
    #pragma unroll
    for (int mt = 0; mt < 2; mt++)
        #pragma unroll
        for (int nt = 0; nt < 8; nt++)
            #pragma unroll
            for (int q = 0; q < 4; q++) acc[mt][nt][q] = 0.f;

    #pragma unroll
    for (int k0 = 0; k0 < HH; k0 += 16) {
        int cb = k0 + qp * 2;
        uint32_t ah[2][4], al[2][4], wh[8][2], wl[8][2];
        #pragma unroll
        for (int mt = 0; mt < 2; mt++) {
            int r = mrow + mt * 16 + qrow;
            uint32_t o00 = (uint32_t)(r * SROW + cb) * 2;
            uint32_t o10 = o00 + 8u * SROW * 2;
            ah[mt][0] = *(const uint32_t*)(smem + OA_H + o00);
            ah[mt][1] = *(const uint32_t*)(smem + OA_H + o10);
            ah[mt][2] = *(const uint32_t*)(smem + OA_H + o00 + 16);
            ah[mt][3] = *(const uint32_t*)(smem + OA_H + o10 + 16);
            if (MODE == 0) {
                al[mt][0] = *(const uint32_t*)(smem + OA_L + o00);
                al[mt][1] = *(const uint32_t*)(smem + OA_L + o10);
                al[mt][2] = *(const uint32_t*)(smem + OA_L + o00 + 16);
                al[mt][3] = *(const uint32_t*)(smem + OA_L + o10 + 16);
            }
        }
        #pragma unroll
        for (int nt = 0; nt < 8; nt++) {
            int n = ncol + nt * 8 + qrow;
            uint32_t o = (uint32_t)(n * SROW + cb) * 2;
            wh[nt][0] = *(const uint32_t*)(smem + OW_H + o);
            wh[nt][1] = *(const uint32_t*)(smem + OW_H + o + 16);
            wl[nt][0] = *(const uint32_t*)(smem + OW_L + o);
            wl[nt][1] = *(const uint32_t*)(smem + OW_L + o + 16);
        }
        #pragma unroll
        for (int mt = 0; mt < 2; mt++)
            #pragma unroll
            for (int nt = 0; nt < 8; nt++) {
                mma_bf16(acc[mt][nt], ah[mt], wh[nt]);
                mma_bf16(acc[mt][nt], ah[mt], wl[nt]);
                if (MODE == 0) mma_bf16(acc[mt][nt], al[mt], wh[nt]);
            }
    }

    #pragma unroll
    for (int mt = 0; mt < 2; mt++) {
        int r0 = rowBase + mrow + mt * 16 + qrow;
        #pragma unroll
        for (int nt = 0; nt < 8; nt++) {
            int cc = ncol + nt * 8 + qp * 2;
            if (r0 < NN) {
                __nv_bfloat162 p = __float22bfloat162_rn(make_float2(acc[mt][nt][0], acc[mt][nt][1]));
                C[(size_t)r0 * 64 + (cc >> 1)] = *reinterpret_cast<uint32_t*>(&p);
            }
            if (r0 + 8 < NN) {
                __nv_bfloat162 p = __float22bfloat162_rn(make_float2(acc[mt][nt][2], acc[mt][nt][3]));
                C[(size_t)(r0 + 8) * 64 + (cc >> 1)] = *reinterpret_cast<uint32_t*>(&p);
            }
        }
    }
}

// ---------------- agg: out[n] = relu(h[n]/deg + sum h[s]*norm + b), bf16 I/O ----
__global__ void agg_kernel(const __nv_bfloat16* __restrict__ h,
                           const float* __restrict__ bias, uint2* __restrict__ outp) {
    int w = (blockIdx.x * blockDim.x + threadIdx.x) >> 5;
    int lane = threadIdx.x & 31;
    if (w >= NN) return;
    int n = w;
    float sn = g_sn[n];
    const uint2* hb = (const uint2*)h;
    float4 hv = bf4(hb[(size_t)n * 32 + lane]);
    float4 acc = make_float4(hv.x * sn, hv.y * sn, hv.z * sn, hv.w * sn);
    float4 acc2 = make_float4(0.f, 0.f, 0.f, 0.f);
    int o = g_off[n], c = g_cnt[n];
    const int2* ep = g_edge + o;
    int j = 0;
    for (; j + 1 < c; j += 2) {
        int2 e0 = ep[j], e1 = ep[j + 1];
        float w0 = __int_as_float(e0.y), w1 = __int_as_float(e1.y);
        float4 v0 = bf4(hb[(size_t)e0.x * 32 + lane]);
        float4 v1 = bf4(hb[(size_t)e1.x * 32 + lane]);
        acc.x += v0.x * w0; acc.y += v0.y * w0; acc.z += v0.z * w0; acc.w += v0.w * w0;
        acc2.x += v1.x * w1; acc2.y += v1.y * w1; acc2.z += v1.z * w1; acc2.w += v1.w * w1;
    }
    if (j < c) {
        int2 e0 = ep[j];
        float w0 = __int_as_float(e0.y);
        float4 v0 = bf4(hb[(size_t)e0.x * 32 + lane]);
        acc.x += v0.x * w0; acc.y += v0.y * w0; acc.z += v0.z * w0; acc.w += v0.w * w0;
    }
    float4 b = *reinterpret_cast<const float4*>(bias + (lane << 2));
    float4 r = make_float4(fmaxf(acc.x + acc2.x + b.x, 0.f), fmaxf(acc.y + acc2.y + b.y, 0.f),
                           fmaxf(acc.z + acc2.z + b.z, 0.f), fmaxf(acc.w + acc2.w + b.w, 0.f));
    outp[(size_t)n * 32 + lane] = pk4(r);
}

// ---------------- pooling (bf16 in, batch sorted; run-accumulate + atomics) -----
#define CHUNK 32
__global__ void pool_kernel(const __nv_bfloat16* __restrict__ h, const int* __restrict__ batch) {
    int w = (blockIdx.x * blockDim.x + threadIdx.x) >> 5;
    int lane = threadIdx.x & 31;
    int start = w * CHUNK;
    if (start >= NN) return;
    int end = min(NN, start + CHUNK);
    const uint2* hb = (const uint2*)h;
    int cur = batch[start];
    float4 acc = make_float4(0.f, 0.f, 0.f, 0.f);
    float cnt = 0.f;
    for (int i = start; i < end; i++) {
        int g = batch[i];
        if (g != cur) {
            float* p = &g_pooled[(size_t)cur * HH + (lane << 2)];
            atomicAdd(p + 0, acc.x); atomicAdd(p + 1, acc.y);
            atomicAdd(p + 2, acc.z); atomicAdd(p + 3, acc.w);
            if (lane == 0) atomicAdd(&g_gcnt[cur], cnt);
            acc = make_float4(0.f, 0.f, 0.f, 0.f); cnt = 0.f; cur = g;
        }
        float4 v = bf4(hb[(size_t)i * 32 + lane]);
        acc.x += v.x; acc.y += v.y; acc.z += v.z; acc.w += v.w;
        cnt += 1.f;
    }
    float* p = &g_pooled[(size_t)cur * HH + (lane << 2)];
    atomicAdd(p + 0, acc.x); atomicAdd(p + 1, acc.y);
    atomicAdd(p + 2, acc.z); atomicAdd(p + 3, acc.w);
    if (lane == 0) atomicAdd(&g_gcnt[cur], cnt);
}

// ---------------- head MLP ----------------
__global__ void mlp_kernel(const float* __restrict__ fW1, const float* __restrict__ fb1,
                           const float* __restrict__ fW2, const float* __restrict__ fb2,
                           float* __restrict__ out) {
    __shared__ float p[HH];
    __shared__ float red[4];
    int g = blockIdx.x, j = threadIdx.x;
    float c = fmaxf(g_gcnt[g], 1.0f);
    p[j] = g_pooled[(size_t)g * HH + j] / c;
    __syncthreads();
    float acc = fb1[j];
    #pragma unroll 8
    for (int k = 0; k < HH; k++) acc += p[k] * fW1[(size_t)j * HH + k];
    float o = fmaxf(acc, 0.f) * fW2[j];
    #pragma unroll
    for (int s = 16; s > 0; s >>= 1) o += __shfl_down_sync(0xffffffffu, o, s);
    if ((j & 31) == 0) red[j >> 5] = o;
    __syncthreads();
    if (j == 0) out[g] = red[0] + red[1] + red[2] + red[3] + fb2[0];
}

// ---------------- launch ----------------
extern "C" void kernel_launch(void* const* d_in, const int* in_sizes, int n_in,
                              void* d_out, int out_size) {
    const float* x     = (const float*)d_in[0];
    const int*   ei    = (const int*)d_in[1];
    const float* ea    = (const float*)d_in[2];
    const int*   batch = (const int*)d_in[3];
    const float* W1    = (const float*)d_in[4];
    const float* b1    = (const float*)d_in[5];
    const float* W2    = (const float*)d_in[6];
    const float* b2    = (const float*)d_in[7];
    const float* fW1   = (const float*)d_in[8];
    const float* fb1   = (const float*)d_in[9];
    const float* fW2   = (const float*)d_in[10];
    const float* fb2   = (const float*)d_in[11];
    float* out = (float*)d_out;

    const int* src = ei;
    const int* dst = ei + EE;

    void *ph0, *ph1;
    cudaGetSymbolAddress(&ph0, g_hb0);
    cudaGetSymbolAddress(&ph1, g_hb1);
    __nv_bfloat16* hb0 = (__nv_bfloat16*)ph0;
    __nv_bfloat16* hb1 = (__nv_bfloat16*)ph1;

    cudaFuncSetAttribute(gemm_mma_kernel<0>, cudaFuncAttributeMaxDynamicSharedMemorySize, GSMEM_BYTES);
    cudaFuncSetAttribute(gemm_mma_kernel<1>, cudaFuncAttributeMaxDynamicSharedMemorySize, GSMEM_BYTES);

    const int tb = 256;
    const int nblk = (NN + tb - 1) / tb;        // 196
    const int e2blk = (EE / 2 + tb - 1) / tb;   // 977
    const int ggrid = (NN + 127) / 128;         // 391

    cudaStream_t s2 = 0;
    cudaEvent_t evA = 0, evB = 0;
    bool par = (cudaStreamCreateWithFlags(&s2, cudaStreamNonBlocking) == cudaSuccess);
    if (par) par = (cudaEventCreateWithFlags(&evA, cudaEventDisableTiming) == cudaSuccess);
    if (par) par = (cudaEventCreateWithFlags(&evB, cudaEventDisableTiming) == cudaSuccess);
    cudaStream_t sc = par ? s2 : (cudaStream_t)0;

    if (par) {
        cudaEventRecord(evA, 0);
        cudaStreamWaitEvent(s2, evA, 0);
    }
    // CSR branch (side stream): init -> count -> scanA -> scanB -> scatter
    setup_kernel<<<nblk, tb, 0, sc>>>();
    count_kernel<<<e2blk, tb, 0, sc>>>((const int2*)dst, (const float2*)ea);
    scanA_kernel<<<nblk, tb, 0, sc>>>();
    scanB_kernel<<<nblk, tb, 0, sc>>>();
    scatter_kernel<<<e2blk, tb, 0, sc>>>((const int2*)src, (const int2*)dst, (const float2*)ea);
    // GEMM1 (main stream, starts immediately — converts W1 in-kernel)
    gemm_mma_kernel<0><<<ggrid, 256, GSMEM_BYTES>>>(x, W1, (uint32_t*)hb0);
    if (par) {
        cudaEventRecord(evB, s2);
        cudaStreamWaitEvent(0, evB, 0);
    }

    // agg1 (standalone, full occupancy) -> GEMM2 (bf16 A) -> agg2 -> pool -> MLP
    agg_kernel<<<((NN * 32) + tb - 1) / tb, tb>>>(hb0, b1, (uint2*)hb1);
    gemm_mma_kernel<1><<<ggrid, 256, GSMEM_BYTES>>>(hb1, W2, (uint32_t*)hb0);
    agg_kernel<<<((NN * 32) + tb - 1) / tb, tb>>>(hb0, b2, (uint2*)hb1);

    int pwarps = (NN + CHUNK - 1) / CHUNK;
    pool_kernel<<<((pwarps * 32) + tb - 1) / tb, tb>>>(hb1, batch);
    mlp_kernel<<<GG, HH>>>(fW1, fb1, fW2, fb2, out);
}

// round 14
// speedup vs baseline: 1.4615x; 1.0436x over previous
#include <cuda_runtime.h>
#include <cuda_bf16.h>
#include <cstdint>

#define NN 50000
#define EE 500000
#define HH 128
#define GG 256

// ---------------- scratch (device globals; no allocs allowed) ----------------
static __device__ __align__(16) __nv_bfloat16 g_hb0[(size_t)NN * HH];  // gemm1 out / gemm2 out
static __device__ __align__(16) __nv_bfloat16 g_hb1[(size_t)NN * HH];  // agg1 out
static __device__ unsigned long long g_packed[NN];  // {cnt:16 | deg fixed-point:48}
static __device__ float g_dinv[NN];
static __device__ float g_sn[NN];      // self-loop coeff = 1/deg
static __device__ int   g_cnt[NN];
static __device__ int   g_off[NN];
static __device__ int   g_part[256];   // scan partials
static __device__ int   g_pos[EE];
static __device__ __align__(8) int2 g_edge[EE];   // CSR: {src, normalized w as bits}
static __device__ __align__(16) float g_pooled[GG * HH];
static __device__ float g_gcnt[GG];

// ---------------- helpers ----------------
__device__ __forceinline__ float4 bf4(uint2 u) {
    __nv_bfloat162 a = *reinterpret_cast<__nv_bfloat162*>(&u.x);
    __nv_bfloat162 b = *reinterpret_cast<__nv_bfloat162*>(&u.y);
    float2 fa = __bfloat1622float2(a), fb = __bfloat1622float2(b);
    return make_float4(fa.x, fa.y, fb.x, fb.y);
}
__device__ __forceinline__ uint2 pk4(float4 v) {
    __nv_bfloat162 a = __float22bfloat162_rn(make_float2(v.x, v.y));
    __nv_bfloat162 b = __float22bfloat162_rn(make_float2(v.z, v.w));
    uint2 u;
    u.x = *reinterpret_cast<uint32_t*>(&a);
    u.y = *reinterpret_cast<uint32_t*>(&b);
    return u;
}
__device__ __forceinline__ void split4(float4 v, uint2& ph, uint2& pl) {
    __nv_bfloat16 h0 = __float2bfloat16(v.x), h1 = __float2bfloat16(v.y);
    __nv_bfloat16 h2 = __float2bfloat16(v.z), h3 = __float2bfloat16(v.w);
    __nv_bfloat16 l0 = __float2bfloat16(v.x - __bfloat162float(h0));
    __nv_bfloat16 l1 = __float2bfloat16(v.y - __bfloat162float(h1));
    __nv_bfloat16 l2 = __float2bfloat16(v.z - __bfloat162float(h2));
    __nv_bfloat16 l3 = __float2bfloat16(v.w - __bfloat162float(h3));
    ph.x = ((uint32_t)__bfloat16_as_ushort(h1) << 16) | __bfloat16_as_ushort(h0);
    ph.y = ((uint32_t)__bfloat16_as_ushort(h3) << 16) | __bfloat16_as_ushort(h2);
    pl.x = ((uint32_t)__bfloat16_as_ushort(l1) << 16) | __bfloat16_as_ushort(l0);
    pl.y = ((uint32_t)__bfloat16_as_ushort(l3) << 16) | __bfloat16_as_ushort(l2);
}

// ---------------- count: ONE packed 64-bit atomic per edge --------------------
// packed += (1<<48) | (u64)(w * 2^32).  Old>>48 = CSR slot.  2 edges/thread.
__global__ void count_kernel(const int2* __restrict__ dst2, const float2* __restrict__ ew2) {
    int e = blockIdx.x * blockDim.x + threadIdx.x;
    if (e >= EE / 2) return;
    int2 d = dst2[e];
    float2 w = ew2[e];
    unsigned long long p0 = (1ull << 48) | (unsigned long long)(w.x * 4294967296.0f);
    unsigned long long p1 = (1ull << 48) | (unsigned long long)(w.y * 4294967296.0f);
    unsigned long long o0 = atomicAdd(&g_packed[d.x], p0);
    g_pos[2 * e] = (int)(o0 >> 48);
    unsigned long long o1 = atomicAdd(&g_packed[d.y], p1);
    g_pos[2 * e + 1] = (int)(o1 >> 48);
}

// ---------------- scanA: warp-shuffle local scan + block totals ---------------
__global__ void scanA_kernel() {        // 196 blocks x 256
    __shared__ int wsum[8];
    int t = threadIdx.x, lane = t & 31, wid = t >> 5;
    int i = blockIdx.x * 256 + t;
    int v = 0;
    if (i < NN) {
        v = (int)(g_packed[i] >> 48);
        g_cnt[i] = v;
    }
    int x = v;
    #pragma unroll
    for (int s = 1; s < 32; s <<= 1) {
        int y = __shfl_up_sync(0xffffffffu, x, s);
        if (lane >= s) x += y;
    }
    if (lane == 31) wsum[wid] = x;
    __syncthreads();
    if (wid == 0) {
        int ws = (lane < 8) ? wsum[lane] : 0;
        #pragma unroll
        for (int s = 1; s < 8; s <<= 1) {
            int y = __shfl_up_sync(0xffffffffu, ws, s);
            if (lane >= s) ws += y;
        }
        if (lane < 8) wsum[lane] = ws;
    }
    __syncthreads();
    int incl = (wid ? wsum[wid - 1] : 0) + x;
    if (i < NN) g_off[i] = incl - v;        // exclusive
    if (t == 255) g_part[blockIdx.x] = incl;
}

// ---------------- scanB: scan 196 partials (shuffle), add base, fuse dinv -----
__global__ void scanB_kernel() {        // 196 blocks x 256
    __shared__ int sps[256];
    __shared__ int wsum[8];
    int t = threadIdx.x, lane = t & 31, wid = t >> 5;
    const int nb = (NN + 255) / 256;    // 196
    int pv = (t < nb) ? g_part[t] : 0;
    int x = pv;
    #pragma unroll
    for (int s = 1; s < 32; s <<= 1) {
        int y = __shfl_up_sync(0xffffffffu, x, s);
        if (lane >= s) x += y;
    }
    if (lane == 31) wsum[wid] = x;
    __syncthreads();
    if (wid == 0) {
        int ws = (lane < 8) ? wsum[lane] : 0;
        #pragma unroll
        for (int s = 1; s < 8; s <<= 1) {
            int y = __shfl_up_sync(0xffffffffu, ws, s);
            if (lane >= s) ws += y;
        }
        if (lane < 8) wsum[lane] = ws;
    }
    __syncthreads();
    sps[t] = (wid ? wsum[wid - 1] : 0) + x;   // inclusive
    __syncthreads();
    int base = blockIdx.x ? sps[blockIdx.x - 1] : 0;
    int i = blockIdx.x * 256 + t;
    if (i < NN) {
        g_off[i] += base;
        unsigned long long p = g_packed[i];
        float deg = 1.0f + (float)(p & 0xFFFFFFFFFFFFull) * 2.3283064365386963e-10f;
        float d = rsqrtf(deg);
        g_dinv[i] = d;
        g_sn[i] = d * d;
    }
}

// ---------------- scatter (edge range [lo,hi) in vec2 units) ------------------
__global__ void scatter_kernel(const int2* __restrict__ src2, const int2* __restrict__ dst2,
                               const float2* __restrict__ ew2, int lo, int hi) {
    int e = lo + blockIdx.x * blockDim.x + threadIdx.x;
    if (e >= hi) return;
    int2 s = src2[e];
    int2 d = dst2[e];
    float2 w = ew2[e];
    int i0 = g_off[d.x] + g_pos[2 * e];
    g_edge[i0] = make_int2(s.x, __float_as_int(g_dinv[s.x] * w.x * g_dinv[d.x]));
    int i1 = g_off[d.y] + g_pos[2 * e + 1];
    g_edge[i1] = make_int2(s.y, __float_as_int(g_dinv[s.y] * w.y * g_dinv[d.y]));
}

// ---------------- HMMA GEMM: C[NN x 128] = A[NN x 128] @ W^T, bf16 out --------
#define SROW 136
#define OA_H 0
#define OA_L (1 * 34816)
#define OW_H (2 * 34816)
#define OW_L (3 * 34816)
#define GSMEM_BYTES (4 * 34816)

__device__ __forceinline__ void mma_bf16(float* c, const uint32_t* a, const uint32_t* b) {
    asm volatile(
        "mma.sync.aligned.m16n8k16.row.col.f32.bf16.bf16.f32 "
        "{%0,%1,%2,%3}, {%4,%5,%6,%7}, {%8,%9}, {%0,%1,%2,%3};"
        : "+f"(c[0]), "+f"(c[1]), "+f"(c[2]), "+f"(c[3])
        : "r"(a[0]), "r"(a[1]), "r"(a[2]), "r"(a[3]), "r"(b[0]), "r"(b[1]));
}

template<int MODE>
__global__ void __launch_bounds__(256) gemm_mma_kernel(
    const void* __restrict__ Ain,
    const float* __restrict__ W,       // fp32 weights, converted in-kernel
    uint32_t* __restrict__ C           // bf16x2-packed output
) {
    extern __shared__ __align__(16) unsigned char smem[];
    int t = threadIdx.x;
    int rowBase = blockIdx.x * 128;

    if (MODE == 0) {
        const float* A = (const float*)Ain;
        #pragma unroll
        for (int i = 0; i < 16; i++) {
            int idx = t + i * 256;
            int row = idx >> 5;
            int col = (idx & 31) << 2;
            float4 v = make_float4(0.f, 0.f, 0.f, 0.f);
            int gr = rowBase + row;
            if (gr < NN) v = *(const float4*)(A + (size_t)gr * HH + col);
            uint2 ph, pl;
            split4(v, ph, pl);
            uint32_t off = (uint32_t)(row * SROW + col) * 2;
            *(uint2*)(smem + OA_H + off) = ph;
            *(uint2*)(smem + OA_L + off) = pl;
        }
    } else {
        const uint2* A = (const uint2*)Ain;   // bf16 rows: 32 uint2 per row
        #pragma unroll
        for (int i = 0; i < 16; i++) {
            int idx = t + i * 256;
            int row = idx >> 5;
            int col = (idx & 31) << 2;
            uint2 v = make_uint2(0u, 0u);
            int gr = rowBase + row;
            if (gr < NN) v = A[(size_t)gr * 32 + (idx & 31)];
            *(uint2*)(smem + OA_H + (uint32_t)(row * SROW + col) * 2) = v;
        }
    }
    // W fp32 -> bf16 hi/lo into smem
    #pragma unroll
    for (int i = 0; i < 16; i++) {
        int idx = t + i * 256;
        int row = idx >> 5;
        int col = (idx & 31) << 2;
        float4 v = *(const float4*)(W + (size_t)row * HH + col);
        uint2 ph, pl;
        split4(v, ph, pl);
        uint32_t off = (uint32_t)(row * SROW + col) * 2;
        *(uint2*)(smem + OW_H + off) = ph;
        *(uint2*)(smem + OW_L + off) = pl;
    }
    __syncthreads();

    int warp = t >> 5, lane = t & 31;
    int mrow = (warp >> 1) * 32;
    int ncol = (warp & 1) * 64;
    int qrow = lane >> 2, qp = lane & 3;

    float acc[2][8][4];
    #pragma unroll
    for (int mt = 0; mt < 2; mt++)
        #pragma unroll
        for (int nt = 0; nt < 8; nt++)
            #pragma unroll
            for (int q = 0; q < 4; q++) acc[mt][nt][q] = 0.f;

    #pragma unroll
    for (int k0 = 0; k0 < HH; k0 += 16) {
        int cb = k0 + qp * 2;
        uint32_t ah[2][4], al[2][4], wh[8][2], wl[8][2];
        #pragma unroll
        for (int mt = 0; mt < 2; mt++) {
            int r = mrow + mt * 16 + qrow;
            uint32_t o00 = (uint32_t)(r * SROW + cb) * 2;
            uint32_t o10 = o00 + 8u * SROW * 2;
            ah[mt][0] = *(const uint32_t*)(smem + OA_H + o00);
            ah[mt][1] = *(const uint32_t*)(smem + OA_H + o10);
            ah[mt][2] = *(const uint32_t*)(smem + OA_H + o00 + 16);
            ah[mt][3] = *(const uint32_t*)(smem + OA_H + o10 + 16);
            if (MODE == 0) {
                al[mt][0] = *(const uint32_t*)(smem + OA_L + o00);
                al[mt][1] = *(const uint32_t*)(smem + OA_L + o10);
                al[mt][2] = *(const uint32_t*)(smem + OA_L + o00 + 16);
                al[mt][3] = *(const uint32_t*)(smem + OA_L + o10 + 16);
            }
        }
        #pragma unroll
        for (int nt = 0; nt < 8; nt++) {
            int n = ncol + nt * 8 + qrow;
            uint32_t o = (uint32_t)(n * SROW + cb) * 2;
            wh[nt][0] = *(const uint32_t*)(smem + OW_H + o);
            wh[nt][1] = *(const uint32_t*)(smem + OW_H + o + 16);
            wl[nt][0] = *(const uint32_t*)(smem + OW_L + o);
            wl[nt][1] = *(const uint32_t*)(smem + OW_L + o + 16);
        }
        #pragma unroll
        for (int mt = 0; mt < 2; mt++)
            #pragma unroll
            for (int nt = 0; nt < 8; nt++) {
                mma_bf16(acc[mt][nt], ah[mt], wh[nt]);
                mma_bf16(acc[mt][nt], ah[mt], wl[nt]);
                if (MODE == 0) mma_bf16(acc[mt][nt], al[mt], wh[nt]);
            }
    }

    #pragma unroll
    for (int mt = 0; mt < 2; mt++) {
        int r0 = rowBase + mrow + mt * 16 + qrow;
        #pragma unroll
        for (int nt = 0; nt < 8; nt++) {
            int cc = ncol + nt * 8 + qp * 2;
            if (r0 < NN) {
                __nv_bfloat162 p = __float22bfloat162_rn(make_float2(acc[mt][nt][0], acc[mt][nt][1]));
                C[(size_t)r0 * 64 + (cc >> 1)] = *reinterpret_cast<uint32_t*>(&p);
            }
            if (r0 + 8 < NN) {
                __nv_bfloat162 p = __float22bfloat162_rn(make_float2(acc[mt][nt][2], acc[mt][nt][3]));
                C[(size_t)(r0 + 8) * 64 + (cc >> 1)] = *reinterpret_cast<uint32_t*>(&p);
            }
        }
    }
}

// ---------------- agg1: out[n] = relu(h[n]/deg + sum h[s]*norm + b), bf16 I/O --
__global__ void agg_kernel(const __nv_bfloat16* __restrict__ h,
                           const float* __restrict__ bias, uint2* __restrict__ outp) {
    int w = (blockIdx.x * blockDim.x + threadIdx.x) >> 5;
    int lane = threadIdx.x & 31;
    if (w >= NN) return;
    int n = w;
    float sn = g_sn[n];
    const uint2* hb = (const uint2*)h;
    float4 hv = bf4(hb[(size_t)n * 32 + lane]);
    float4 acc = make_float4(hv.x * sn, hv.y * sn, hv.z * sn, hv.w * sn);
    float4 acc2 = make_float4(0.f, 0.f, 0.f, 0.f);
    int o = g_off[n], c = g_cnt[n];
    const int2* ep = g_edge + o;
    int j = 0;
    for (; j + 1 < c; j += 2) {
        int2 e0 = ep[j], e1 = ep[j + 1];
        float w0 = __int_as_float(e0.y), w1 = __int_as_float(e1.y);
        float4 v0 = bf4(hb[(size_t)e0.x * 32 + lane]);
        float4 v1 = bf4(hb[(size_t)e1.x * 32 + lane]);
        acc.x += v0.x * w0; acc.y += v0.y * w0; acc.z += v0.z * w0; acc.w += v0.w * w0;
        acc2.x += v1.x * w1; acc2.y += v1.y * w1; acc2.z += v1.z * w1; acc2.w += v1.w * w1;
    }
    if (j < c) {
        int2 e0 = ep[j];
        float w0 = __int_as_float(e0.y);
        float4 v0 = bf4(hb[(size_t)e0.x * 32 + lane]);
        acc.x += v0.x * w0; acc.y += v0.y * w0; acc.z += v0.z * w0; acc.w += v0.w * w0;
    }
    float4 b = *reinterpret_cast<const float4*>(bias + (lane << 2));
    float4 r = make_float4(fmaxf(acc.x + acc2.x + b.x, 0.f), fmaxf(acc.y + acc2.y + b.y, 0.f),
                           fmaxf(acc.z + acc2.z + b.z, 0.f), fmaxf(acc.w + acc2.w + b.w, 0.f));
    outp[(size_t)n * 32 + lane] = pk4(r);
}

// ---------------- fused agg2 + pool: one warp per 8 nodes, fp32 throughout -----
#define ANODES 8
__global__ void aggpool_kernel(const __nv_bfloat16* __restrict__ h,
                               const float* __restrict__ bias,
                               const int* __restrict__ batch) {
    int w = (blockIdx.x * blockDim.x + threadIdx.x) >> 5;
    int lane = threadIdx.x & 31;
    int start = w * ANODES;
    if (start >= NN) return;
    int end = min(NN, start + ANODES);
    const uint2* hb = (const uint2*)h;
    float4 b = *reinterpret_cast<const float4*>(bias + (lane << 2));
    int cur = batch[start];
    float4 pacc = make_float4(0.f, 0.f, 0.f, 0.f);
    float pcnt = 0.f;
    for (int n = start; n < end; n++) {
        int g = batch[n];
        if (g != cur) {
            float* p = &g_pooled[(size_t)cur * HH + (lane << 2)];
            atomicAdd(p + 0, pacc.x); atomicAdd(p + 1, pacc.y);
            atomicAdd(p + 2, pacc.z); atomicAdd(p + 3, pacc.w);
            if (lane == 0) atomicAdd(&g_gcnt[cur], pcnt);
            pacc = make_float4(0.f, 0.f, 0.f, 0.f); pcnt = 0.f; cur = g;
        }
        float sn = g_sn[n];
        float4 hv = bf4(hb[(size_t)n * 32 + lane]);
        float4 acc = make_float4(hv.x * sn, hv.y * sn, hv.z * sn, hv.w * sn);
        float4 acc2 = make_float4(0.f, 0.f, 0.f, 0.f);
        int o = g_off[n], c = g_cnt[n];
        const int2* ep = g_edge + o;
        int j = 0;
        for (; j + 1 < c; j += 2) {
            int2 e0 = ep[j], e1 = ep[j + 1];
            float w0 = __int_as_float(e0.y), w1 = __int_as_float(e1.y);
            float4 v0 = bf4(hb[(size_t)e0.x * 32 + lane]);
            float4 v1 = bf4(hb[(size_t)e1.x * 32 + lane]);
            acc.x += v0.x * w0; acc.y += v0.y * w0; acc.z += v0.z * w0; acc.w += v0.w * w0;
            acc2.x += v1.x * w1; acc2.y += v1.y * w1; acc2.z += v1.z * w1; acc2.w += v1.w * w1;
        }
        if (j < c) {
            int2 e0 = ep[j];
            float w0 = __int_as_float(e0.y);
            float4 v0 = bf4(hb[(size_t)e0.x * 32 + lane]);
            acc.x += v0.x * w0; acc.y += v0.y * w0; acc.z += v0.z * w0; acc.w += v0.w * w0;
        }
        pacc.x += fmaxf(acc.x + acc2.x + b.x, 0.f);
        pacc.y += fmaxf(acc.y + acc2.y + b.y, 0.f);
        pacc.z += fmaxf(acc.z + acc2.z + b.z, 0.f);
        pacc.w += fmaxf(acc.w + acc2.w + b.w, 0.f);
        pcnt += 1.f;
    }
    float* p = &g_pooled[(size_t)cur * HH + (lane << 2)];
    atomicAdd(p + 0, pacc.x); atomicAdd(p + 1, pacc.y);
    atomicAdd(p + 2, pacc.z); atomicAdd(p + 3, pacc.w);
    if (lane == 0) atomicAdd(&g_gcnt[cur], pcnt);
}

// ---------------- head MLP ----------------
__global__ void mlp_kernel(const float* __restrict__ fW1, const float* __restrict__ fb1,
                           const float* __restrict__ fW2, const float* __restrict__ fb2,
                           float* __restrict__ out) {
    __shared__ float p[HH];
    __shared__ float red[4];
    int g = blockIdx.x, j = threadIdx.x;
    float c = fmaxf(g_gcnt[g], 1.0f);
    p[j] = g_pooled[(size_t)g * HH + j] / c;
    __syncthreads();
    float acc = fb1[j];
    #pragma unroll 8
    for (int k = 0; k < HH; k++) acc += p[k] * fW1[(size_t)j * HH + k];
    float o = fmaxf(acc, 0.f) * fW2[j];
    #pragma unroll
    for (int s = 16; s > 0; s >>= 1) o += __shfl_down_sync(0xffffffffu, o, s);
    if ((j & 31) == 0) red[j >> 5] = o;
    __syncthreads();
    if (j == 0) out[g] = red[0] + red[1] + red[2] + red[3] + fb2[0];
}

// ---------------- launch ----------------
extern "C" void kernel_launch(void* const* d_in, const int* in_sizes, int n_in,
                              void* d_out, int out_size) {
    const float* x     = (const float*)d_in[0];
    const int*   ei    = (const int*)d_in[1];
    const float* ea    = (const float*)d_in[2];
    const int*   batch = (const int*)d_in[3];
    const float* W1    = (const float*)d_in[4];
    const float* b1    = (const float*)d_in[5];
    const float* W2    = (const float*)d_in[6];
    const float* b2    = (const float*)d_in[7];
    const float* fW1   = (const float*)d_in[8];
    const float* fb1   = (const float*)d_in[9];
    const float* fW2   = (const float*)d_in[10];
    const float* fb2   = (const float*)d_in[11];
    float* out = (float*)d_out;

    const int* src = ei;
    const int* dst = ei + EE;

    void *ph0, *ph1, *ppk, *ppl, *pgc;
    cudaGetSymbolAddress(&ph0, g_hb0);
    cudaGetSymbolAddress(&ph1, g_hb1);
    cudaGetSymbolAddress(&ppk, g_packed);
    cudaGetSymbolAddress(&ppl, g_pooled);
    cudaGetSymbolAddress(&pgc, g_gcnt);
    __nv_bfloat16* hb0 = (__nv_bfloat16*)ph0;
    __nv_bfloat16* hb1 = (__nv_bfloat16*)ph1;

    cudaFuncSetAttribute(gemm_mma_kernel<0>, cudaFuncAttributeMaxDynamicSharedMemorySize, GSMEM_BYTES);
    cudaFuncSetAttribute(gemm_mma_kernel<1>, cudaFuncAttributeMaxDynamicSharedMemorySize, GSMEM_BYTES);

    const int tb = 256;
    const int nblk = (NN + tb - 1) / tb;        // 196
    const int eh = EE / 4;                      // half of the vec2 range
    const int ehblk = (eh + tb - 1) / tb;       // 489
    const int ggrid = (NN + 127) / 128;         // 391

    cudaStream_t s2 = 0;
    cudaEvent_t evA = 0, evB = 0, evC = 0;
    bool par = (cudaStreamCreateWithFlags(&s2, cudaStreamNonBlocking) == cudaSuccess);
    if (par) par = (cudaEventCreateWithFlags(&evA, cudaEventDisableTiming) == cudaSuccess);
    if (par) par = (cudaEventCreateWithFlags(&evB, cudaEventDisableTiming) == cudaSuccess);
    if (par) par = (cudaEventCreateWithFlags(&evC, cudaEventDisableTiming) == cudaSuccess);
    cudaStream_t sc = par ? s2 : (cudaStream_t)0;

    if (par) {
        cudaEventRecord(evA, 0);
        cudaStreamWaitEvent(s2, evA, 0);
    }
    // CSR branch (side stream): zero -> count -> scanA -> scanB
    cudaMemsetAsync(ppk, 0, (size_t)NN * 8, sc);
    cudaMemsetAsync(ppl, 0, (size_t)GG * HH * 4, sc);
    cudaMemsetAsync(pgc, 0, (size_t)GG * 4, sc);
    count_kernel<<<(EE / 2 + tb - 1) / tb, tb, 0, sc>>>((const int2*)dst, (const float2*)ea);
    scanA_kernel<<<nblk, tb, 0, sc>>>();
    scanB_kernel<<<nblk, tb, 0, sc>>>();
    if (par) cudaEventRecord(evB, s2);
    // GEMM1 (main stream, runs concurrently with the CSR chain)
    gemm_mma_kernel<0><<<ggrid, 256, GSMEM_BYTES>>>(x, W1, (uint32_t*)hb0);
    if (par) cudaStreamWaitEvent(0, evB, 0);
    // scatter split across both streams (main is idle after GEMM1 here)
    scatter_kernel<<<ehblk, tb>>>((const int2*)src, (const int2*)dst, (const float2*)ea, 0, eh);
    scatter_kernel<<<ehblk, tb, 0, sc>>>((const int2*)src, (const int2*)dst, (const float2*)ea, eh, EE / 2);
    if (par) {
        cudaEventRecord(evC, s2);
        cudaStreamWaitEvent(0, evC, 0);
    }

    // agg1 -> GEMM2 (bf16 A) -> fused agg2+pool -> MLP head
    agg_kernel<<<((NN * 32) + tb - 1) / tb, tb>>>(hb0, b1, (uint2*)hb1);
    gemm_mma_kernel<1><<<ggrid, 256, GSMEM_BYTES>>>(hb1, W2, (uint32_t*)hb0);
    int awarps = (NN + ANODES - 1) / ANODES;    // 6250
    aggpool_kernel<<<((awarps * 32) + tb - 1) / tb, tb>>>(hb0, b2, batch);
    mlp_kernel<<<GG, HH>>>(fW1, fb1, fW2, fb2, out);
}